// round 2
// baseline (speedup 1.0000x reference)
#include <cuda_runtime.h>
#include <cuda_bf16.h>

// Problem dims (fixed by reference)
#define BB   16
#define TT   256
#define KK   128
#define DE   256
#define DK   256
#define UU   128

// Scratch for the two input projections (allocation-free rule -> __device__ globals)
__device__ float g_E [BB * TT * UU];   // [B*T, U]  enc@W1 + b1   (2 MB)
__device__ float g_Kp[BB * KK * UU];   // [B*K, U]  kn @W2 + b2   (1 MB)

__device__ __forceinline__ float fast_tanh(float x) {
    float y;
    asm("tanh.approx.f32 %0, %1;" : "=f"(y) : "f"(x));
    return y;
}

// ---------------------------------------------------------------------------
// Prologue: compute g_E and g_Kp. 4 rows per CTA, 128 threads (thread = u).
// Blocks [0, 1024)  -> E rows   (4096 rows of enc[4096,256] @ W1[256,128])
// Blocks [1024,1536)-> Kp rows  (2048 rows of kn [2048,256] @ W2[256,128])
// ---------------------------------------------------------------------------
__global__ void __launch_bounds__(128) prep_kernel(
    const float* __restrict__ enc, const float* __restrict__ kn,
    const float* __restrict__ W1,  const float* __restrict__ b1,
    const float* __restrict__ W2,  const float* __restrict__ b2)
{
    const bool isE = (blockIdx.x < 1024);
    const int  rbase = (isE ? blockIdx.x : (blockIdx.x - 1024)) * 4;
    const float* __restrict__ X = isE ? enc : kn;
    const float* __restrict__ W = isE ? W1  : W2;
    const float* __restrict__ bias = isE ? b1 : b2;
    float* __restrict__ O = isE ? g_E : g_Kp;

    __shared__ float sX[4][DE];
    const int tid = threadIdx.x;  // 0..127 ; also the output u index
    #pragma unroll
    for (int r = 0; r < 4; r++) {
        sX[r][tid]       = X[(rbase + r) * DE + tid];
        sX[r][tid + 128] = X[(rbase + r) * DE + tid + 128];
    }
    __syncthreads();

    float a0 = 0.f, a1 = 0.f, a2 = 0.f, a3 = 0.f;
    #pragma unroll 8
    for (int d = 0; d < DE; d++) {
        const float w = W[d * UU + tid];       // coalesced; L1-resident after first pass
        a0 = fmaf(sX[0][d], w, a0);
        a1 = fmaf(sX[1][d], w, a1);
        a2 = fmaf(sX[2][d], w, a2);
        a3 = fmaf(sX[3][d], w, a3);
    }
    const float bb = bias[tid];
    O[(rbase + 0) * UU + tid] = a0 + bb;
    O[(rbase + 1) * UU + tid] = a1 + bb;
    O[(rbase + 2) * UU + tid] = a2 + bb;
    O[(rbase + 3) * UU + tid] = a3 + bb;
}

// ---------------------------------------------------------------------------
// Main kernel: one CTA per (b,t). 256 threads = 8 warps.
//   phase 1: 8 warps x 16 k-rows: score[k] = sum_u tanh(E_u + Kp_u) * V_u
//   phase 2: warp 0 softmax over K=128
//   phase 3: thread d (0..255): context[d] = sum_k attn[k] * kn[b,k,d]
// ---------------------------------------------------------------------------
__global__ void __launch_bounds__(256) attn_kernel(
    const float* __restrict__ kn, const float* __restrict__ V,
    float* __restrict__ out)
{
    const int b = blockIdx.x >> 8;       // / TT
    const int t = blockIdx.x & (TT - 1); // % TT

    __shared__ float sE[UU];
    __shared__ float sV[UU];
    __shared__ float sScore[KK];
    __shared__ float sAttn[KK];

    const int tid  = threadIdx.x;
    const int w    = tid >> 5;
    const int lane = tid & 31;

    if (tid < UU) {
        sE[tid] = g_E[(b * TT + t) * UU + tid];
        sV[tid] = V[tid];
    }
    __syncthreads();

    // lane handles u = lane + 32*j, j=0..3 (MUFU ILP = 4)
    const float e0 = sE[lane], e1 = sE[lane + 32], e2 = sE[lane + 64], e3 = sE[lane + 96];
    const float v0 = sV[lane], v1 = sV[lane + 32], v2 = sV[lane + 64], v3 = sV[lane + 96];

    const float* __restrict__ KpB = g_Kp + b * KK * UU;

    #pragma unroll 2
    for (int k = w; k < KK; k += 8) {
        const float* __restrict__ row = KpB + k * UU;
        const float a0 = fast_tanh(e0 + row[lane]);
        const float a1 = fast_tanh(e1 + row[lane + 32]);
        const float a2 = fast_tanh(e2 + row[lane + 64]);
        const float a3 = fast_tanh(e3 + row[lane + 96]);
        float acc = a0 * v0;
        acc = fmaf(a1, v1, acc);
        acc = fmaf(a2, v2, acc);
        acc = fmaf(a3, v3, acc);
        #pragma unroll
        for (int off = 16; off; off >>= 1)
            acc += __shfl_xor_sync(0xffffffffu, acc, off);
        if (lane == 0) sScore[k] = acc;
    }
    __syncthreads();

    // softmax over K (bV is constant over k -> cancels in softmax)
    if (w == 0) {
        float s0 = sScore[lane], s1 = sScore[lane + 32];
        float s2 = sScore[lane + 64], s3 = sScore[lane + 96];
        float m = fmaxf(fmaxf(s0, s1), fmaxf(s2, s3));
        #pragma unroll
        for (int off = 16; off; off >>= 1)
            m = fmaxf(m, __shfl_xor_sync(0xffffffffu, m, off));
        const float p0 = __expf(s0 - m), p1 = __expf(s1 - m);
        const float p2 = __expf(s2 - m), p3 = __expf(s3 - m);
        float sum = (p0 + p1) + (p2 + p3);
        #pragma unroll
        for (int off = 16; off; off >>= 1)
            sum += __shfl_xor_sync(0xffffffffu, sum, off);
        const float inv = 1.0f / sum;
        sAttn[lane]      = p0 * inv;
        sAttn[lane + 32] = p1 * inv;
        sAttn[lane + 64] = p2 * inv;
        sAttn[lane + 96] = p3 * inv;
    }
    __syncthreads();

    // context: thread = d (0..255); coalesced LDG over kn, broadcast LDS of attn
    const float* __restrict__ knB = kn + b * KK * DK + tid;
    float acc = 0.f;
    #pragma unroll 8
    for (int k = 0; k < KK; k++)
        acc = fmaf(sAttn[k], knB[k * DK], acc);
    out[(b * TT + t) * DK + tid] = acc;
}

extern "C" void kernel_launch(void* const* d_in, const int* in_sizes, int n_in,
                              void* d_out, int out_size)
{
    // metadata order: knowledge_onehot, encoder_outputs, W1, b1, W2, b2, V, bV
    const float* kn  = (const float*)d_in[0];
    const float* enc = (const float*)d_in[1];
    const float* W1  = (const float*)d_in[2];
    const float* b1  = (const float*)d_in[3];
    const float* W2  = (const float*)d_in[4];
    const float* b2  = (const float*)d_in[5];
    const float* V   = (const float*)d_in[6];
    float* out = (float*)d_out;

    prep_kernel<<<1536, 128>>>(enc, kn, W1, b1, W2, b2);
    attn_kernel<<<BB * TT, 256>>>(kn, V, out);
}

// round 3
// speedup vs baseline: 1.9720x; 1.9720x over previous
#include <cuda_runtime.h>
#include <cuda_bf16.h>

// Problem dims (fixed by reference)
#define BB   16
#define TT   256
#define KK   128
#define DE   256
#define DK   256
#define UU   128

#define TILE_T 16                 // t-rows per CTA in the attention kernel

// Scratch (allocation-free rule -> __device__ globals)
__device__ float g_E  [BB * TT * UU];   // [B*T, U]     enc@W1 + b1   (2 MB)
__device__ float g_KpT[BB * UU * KK];   // [B, U, K]    (kn@W2 + b2)^T per batch (1 MB)

__device__ __forceinline__ float fast_tanh(float x) {
    float y;
    asm("tanh.approx.f32 %0, %1;" : "=f"(y) : "f"(x));
    return y;
}

// ---------------------------------------------------------------------------
// Prologue: 8 rows per CTA, 128 threads (thread = u).
// Blocks [0, 512)  -> E rows   (4096 rows of enc[4096,256] @ W1[256,128])
// Blocks [512,768) -> Kp rows  (2048 rows of kn [2048,256] @ W2[256,128]),
//                     written TRANSPOSED per batch: g_KpT[b][u][k]
// ---------------------------------------------------------------------------
__global__ void __launch_bounds__(128) prep_kernel(
    const float* __restrict__ enc, const float* __restrict__ kn,
    const float* __restrict__ W1,  const float* __restrict__ b1,
    const float* __restrict__ W2,  const float* __restrict__ b2)
{
    const bool isE  = (blockIdx.x < 512);
    const int  rbase = (isE ? blockIdx.x : (blockIdx.x - 512)) * 8;
    const float* __restrict__ X    = isE ? enc : kn;
    const float* __restrict__ W    = isE ? W1  : W2;
    const float* __restrict__ bias = isE ? b1  : b2;

    __shared__ float sX[8][DE];
    const int tid = threadIdx.x;  // 0..127 ; also the output u index
    #pragma unroll
    for (int r = 0; r < 8; r++) {
        sX[r][tid]       = X[(rbase + r) * DE + tid];
        sX[r][tid + 128] = X[(rbase + r) * DE + tid + 128];
    }
    __syncthreads();

    float a[8];
    #pragma unroll
    for (int r = 0; r < 8; r++) a[r] = 0.f;

    #pragma unroll 4
    for (int d = 0; d < DE; d++) {
        const float w = W[d * UU + tid];       // coalesced; L1-resident
        #pragma unroll
        for (int r = 0; r < 8; r++)
            a[r] = fmaf(sX[r][d], w, a[r]);
    }
    const float bb = bias[tid];

    if (isE) {
        #pragma unroll
        for (int r = 0; r < 8; r++)
            g_E[(rbase + r) * UU + tid] = a[r] + bb;
    } else {
        #pragma unroll
        for (int r = 0; r < 8; r++) {
            const int row = rbase + r;          // global knowledge row = b*K + k
            const int b = row >> 7;
            const int k = row & (KK - 1);
            g_KpT[(b * UU + tid) * KK + k] = a[r] + bb;
        }
    }
}

// ---------------------------------------------------------------------------
// Main kernel: one CTA per (b, t-tile of 16). 256 threads = 8 warps.
// Dynamic smem: sKpT[U][K] 64KB | sE[16][U] 8KB | sSc[16][K] 8KB | sV[U] 0.5KB
//   phase 1: thread (k = tid&127, th = tid>>7) owns 8 t's:
//            sc[t][k] = sum_u tanh(e[t][u] + kpT[u][k]) * v[u]   -- no shuffles
//   phase 2: warp w: softmax over K for t = 2w, 2w+1 (in place)
//   phase 3: thread = d: context[t][d] = sum_k attn[t][k] * kn[b][k][d]
// ---------------------------------------------------------------------------
__global__ void __launch_bounds__(256, 2) attn_kernel(
    const float* __restrict__ kn, const float* __restrict__ V,
    float* __restrict__ out)
{
    extern __shared__ float sm[];
    float* __restrict__ sKpT = sm;                       // 128*128
    float* __restrict__ sE   = sm + UU * KK;             // 16*128
    float* __restrict__ sSc  = sE + TILE_T * UU;         // 16*128
    float* __restrict__ sV   = sSc + TILE_T * KK;        // 128

    const int b  = blockIdx.x >> 4;
    const int t0 = (blockIdx.x & 15) * TILE_T;
    const int tid  = threadIdx.x;
    const int w    = tid >> 5;
    const int lane = tid & 31;

    // ---- stage: KpT block (64KB), E tile (8KB), V ----
    {
        const float4* __restrict__ src = (const float4*)(g_KpT + b * UU * KK);
        float4* __restrict__ dst = (float4*)sKpT;
        #pragma unroll
        for (int j = 0; j < 16; j++)                     // 4096 float4 / 256 thr
            dst[tid + 256 * j] = src[tid + 256 * j];

        const float4* __restrict__ esrc = (const float4*)(g_E + (b * TT + t0) * UU);
        float4* __restrict__ edst = (float4*)sE;
        #pragma unroll
        for (int j = 0; j < 2; j++)                      // 512 float4 / 256 thr
            edst[tid + 256 * j] = esrc[tid + 256 * j];

        if (tid < UU) sV[tid] = V[tid];
    }
    __syncthreads();

    // ---- phase 1: scores ----
    {
        const int k  = tid & (KK - 1);
        const int th = tid >> 7;                         // 0 or 1 -> t half
        const float* __restrict__ eB = sE + th * 8 * UU;

        float acc[8];
        #pragma unroll
        for (int i = 0; i < 8; i++) acc[i] = 0.f;

        #pragma unroll 2
        for (int u = 0; u < UU; u++) {
            const float kp = sKpT[u * KK + k];           // conflict-free (lane->k)
            const float v  = sV[u];                      // broadcast
            #pragma unroll
            for (int i = 0; i < 8; i++)                  // 8 indep tanh chains
                acc[i] = fmaf(fast_tanh(eB[i * UU + u] + kp), v, acc[i]);
        }
        #pragma unroll
        for (int i = 0; i < 8; i++)
            sSc[(th * 8 + i) * KK + k] = acc[i];
    }
    __syncthreads();

    // ---- phase 2: softmax over K, warp w handles t = 2w, 2w+1 (in place) ----
    {
        #pragma unroll
        for (int r = 0; r < 2; r++) {
            float* __restrict__ row = sSc + (2 * w + r) * KK;
            float s0 = row[lane], s1 = row[lane + 32];
            float s2 = row[lane + 64], s3 = row[lane + 96];
            float m = fmaxf(fmaxf(s0, s1), fmaxf(s2, s3));
            #pragma unroll
            for (int off = 16; off; off >>= 1)
                m = fmaxf(m, __shfl_xor_sync(0xffffffffu, m, off));
            const float p0 = __expf(s0 - m), p1 = __expf(s1 - m);
            const float p2 = __expf(s2 - m), p3 = __expf(s3 - m);
            float sum = (p0 + p1) + (p2 + p3);
            #pragma unroll
            for (int off = 16; off; off >>= 1)
                sum += __shfl_xor_sync(0xffffffffu, sum, off);
            const float inv = 1.0f / sum;
            row[lane]      = p0 * inv;
            row[lane + 32] = p1 * inv;
            row[lane + 64] = p2 * inv;
            row[lane + 96] = p3 * inv;
        }
    }
    __syncthreads();

    // ---- phase 3: context, thread = d, 16 accumulators over the t-tile ----
    {
        const float* __restrict__ knB = kn + b * KK * DK + tid;
        float cacc[TILE_T];
        #pragma unroll
        for (int i = 0; i < TILE_T; i++) cacc[i] = 0.f;

        #pragma unroll 2
        for (int k = 0; k < KK; k++) {
            const float kv = knB[k * DK];                // coalesced, L1/L2-hit
            #pragma unroll
            for (int i = 0; i < TILE_T; i++)
                cacc[i] = fmaf(sSc[i * KK + k], kv, cacc[i]);
        }
        float* __restrict__ oB = out + (b * TT + t0) * DK + tid;
        #pragma unroll
        for (int i = 0; i < TILE_T; i++)
            oB[i * DK] = cacc[i];
    }
}

extern "C" void kernel_launch(void* const* d_in, const int* in_sizes, int n_in,
                              void* d_out, int out_size)
{
    // metadata order: knowledge_onehot, encoder_outputs, W1, b1, W2, b2, V, bV
    const float* kn  = (const float*)d_in[0];
    const float* enc = (const float*)d_in[1];
    const float* W1  = (const float*)d_in[2];
    const float* b1  = (const float*)d_in[3];
    const float* W2  = (const float*)d_in[4];
    const float* b2  = (const float*)d_in[5];
    const float* V   = (const float*)d_in[6];
    float* out = (float*)d_out;

    const int smem = (UU * KK + TILE_T * UU + TILE_T * KK + UU) * sizeof(float);
    static bool attr_set = false;   // idempotent attribute, not a work guard
    if (!attr_set) {
        cudaFuncSetAttribute(attn_kernel, cudaFuncAttributeMaxDynamicSharedMemorySize, smem);
        attr_set = true;
    }

    prep_kernel<<<768, 128>>>(enc, kn, W1, b1, W2, b2);
    attn_kernel<<<BB * (TT / TILE_T), 256, smem>>>(kn, V, out);
}

// round 5
// speedup vs baseline: 2.1009x; 1.0654x over previous
#include <cuda_runtime.h>
#include <cuda_bf16.h>

// Problem dims (fixed by reference)
#define BB   16
#define TT   256
#define KK   128
#define DE   256
#define DK   256
#define UU   128

#define TILE_T 8                  // t-rows per CTA in the attention kernel

// Scratch (allocation-free rule -> __device__ globals)
__device__ float g_E  [BB * TT * UU];   // [B*T, U]     enc@W1 + b1   (2 MB)
__device__ float g_KpT[BB * UU * KK];   // [B, U, K]    (kn@W2 + b2)^T per batch (1 MB)

__device__ __forceinline__ float fast_tanh(float x) {
    float y;
    asm("tanh.approx.f32 %0, %1;" : "=f"(y) : "f"(x));
    return y;
}

// ---------------------------------------------------------------------------
// Prologue: 8 rows per CTA, 128 threads (thread = u).
// Blocks [0, 512)  -> E rows   (4096 rows of enc[4096,256] @ W1[256,128])
// Blocks [512,768) -> Kp rows  (2048 rows of kn [2048,256] @ W2[256,128]),
//                     written TRANSPOSED per batch: g_KpT[b][u][k]
// ---------------------------------------------------------------------------
__global__ void __launch_bounds__(128) prep_kernel(
    const float* __restrict__ enc, const float* __restrict__ kn,
    const float* __restrict__ W1,  const float* __restrict__ b1,
    const float* __restrict__ W2,  const float* __restrict__ b2)
{
    const bool isE  = (blockIdx.x < 512);
    const int  rbase = (isE ? blockIdx.x : (blockIdx.x - 512)) * 8;
    const float* __restrict__ X    = isE ? enc : kn;
    const float* __restrict__ W    = isE ? W1  : W2;
    const float* __restrict__ bias = isE ? b1  : b2;

    __shared__ float sX[8][DE];
    const int tid = threadIdx.x;  // 0..127 ; also the output u index
    #pragma unroll
    for (int r = 0; r < 8; r++) {
        sX[r][tid]       = X[(rbase + r) * DE + tid];
        sX[r][tid + 128] = X[(rbase + r) * DE + tid + 128];
    }
    __syncthreads();

    float a[8];
    #pragma unroll
    for (int r = 0; r < 8; r++) a[r] = 0.f;

    #pragma unroll 4
    for (int d = 0; d < DE; d++) {
        const float w = W[d * UU + tid];       // coalesced; L1-resident
        #pragma unroll
        for (int r = 0; r < 8; r++)
            a[r] = fmaf(sX[r][d], w, a[r]);
    }
    const float bb = bias[tid];

    if (isE) {
        #pragma unroll
        for (int r = 0; r < 8; r++)
            g_E[(rbase + r) * UU + tid] = a[r] + bb;
    } else {
        #pragma unroll
        for (int r = 0; r < 8; r++) {
            const int row = rbase + r;          // global knowledge row = b*K + k
            const int b = row >> 7;
            const int k = row & (KK - 1);
            g_KpT[(b * UU + tid) * KK + k] = a[r] + bb;
        }
    }
}

// ---------------------------------------------------------------------------
// Main kernel: one CTA per (b, t-tile of 8). 256 threads = 8 warps, 3 CTAs/SM.
// Dynamic smem: sKpT[U][K] 64KB | sE[8][U] 4KB | sSc[8][K] 4KB | sV[U] 0.5KB
//   phase 1: thread (k = tid&127, th = tid>>7) owns 4 t's; u vectorized by 4:
//            sc[t][k] = sum_u tanh(e[t][u] + kpT[u][k]) * v[u]   -- no shuffles
//   phase 2: warp w: softmax over K for t = w (in place)
//   phase 3: thread = d: context[t][d] = sum_k attn[t][k] * kn[b][k][d]
// ---------------------------------------------------------------------------
__global__ void __launch_bounds__(256, 3) attn_kernel(
    const float* __restrict__ kn, const float* __restrict__ V,
    float* __restrict__ out)
{
    extern __shared__ float sm[];
    float* __restrict__ sKpT = sm;                       // 128*128
    float* __restrict__ sE   = sm + UU * KK;             // 8*128
    float* __restrict__ sSc  = sE + TILE_T * UU;         // 8*128
    float* __restrict__ sV   = sSc + TILE_T * KK;        // 128

    const int b  = blockIdx.x >> 5;                      // / (TT/TILE_T)
    const int t0 = (blockIdx.x & 31) * TILE_T;
    const int tid  = threadIdx.x;
    const int w    = tid >> 5;
    const int lane = tid & 31;

    // ---- stage: KpT block (64KB), E tile (4KB), V ----
    {
        const float4* __restrict__ src = (const float4*)(g_KpT + b * UU * KK);
        float4* __restrict__ dst = (float4*)sKpT;
        #pragma unroll
        for (int j = 0; j < 16; j++)                     // 4096 float4 / 256 thr
            dst[tid + 256 * j] = src[tid + 256 * j];

        const float4* __restrict__ esrc = (const float4*)(g_E + (b * TT + t0) * UU);
        ((float4*)sE)[tid];                              // no-op silencer
        ((float4*)sE)[tid] = esrc[tid];                  // 256 float4 = 4KB

        if (tid < UU) sV[tid] = V[tid];
    }
    __syncthreads();

    // ---- phase 1: scores (u vectorized by 4 -> 9 LDS per 4 u's) ----
    {
        const int k  = tid & (KK - 1);
        const int th = tid >> 7;                         // 0 or 1 -> t half
        const float* __restrict__ eB = sE + th * 4 * UU;

        float acc0 = 0.f, acc1 = 0.f, acc2 = 0.f, acc3 = 0.f;

        #pragma unroll 2
        for (int u4 = 0; u4 < UU; u4 += 4) {
            const float4 v4 = *(const float4*)(sV + u4);
            const float4 e0 = *(const float4*)(eB + 0 * UU + u4);  // 16B broadcast
            const float4 e1 = *(const float4*)(eB + 1 * UU + u4);
            const float4 e2 = *(const float4*)(eB + 2 * UU + u4);
            const float4 e3 = *(const float4*)(eB + 3 * UU + u4);
            const float kp0 = sKpT[(u4 + 0) * KK + k];   // conflict-free
            const float kp1 = sKpT[(u4 + 1) * KK + k];
            const float kp2 = sKpT[(u4 + 2) * KK + k];
            const float kp3 = sKpT[(u4 + 3) * KK + k];

            acc0 = fmaf(fast_tanh(e0.x + kp0), v4.x, acc0);
            acc1 = fmaf(fast_tanh(e1.x + kp0), v4.x, acc1);
            acc2 = fmaf(fast_tanh(e2.x + kp0), v4.x, acc2);
            acc3 = fmaf(fast_tanh(e3.x + kp0), v4.x, acc3);

            acc0 = fmaf(fast_tanh(e0.y + kp1), v4.y, acc0);
            acc1 = fmaf(fast_tanh(e1.y + kp1), v4.y, acc1);
            acc2 = fmaf(fast_tanh(e2.y + kp1), v4.y, acc2);
            acc3 = fmaf(fast_tanh(e3.y + kp1), v4.y, acc3);

            acc0 = fmaf(fast_tanh(e0.z + kp2), v4.z, acc0);
            acc1 = fmaf(fast_tanh(e1.z + kp2), v4.z, acc1);
            acc2 = fmaf(fast_tanh(e2.z + kp2), v4.z, acc2);
            acc3 = fmaf(fast_tanh(e3.z + kp2), v4.z, acc3);

            acc0 = fmaf(fast_tanh(e0.w + kp3), v4.w, acc0);
            acc1 = fmaf(fast_tanh(e1.w + kp3), v4.w, acc1);
            acc2 = fmaf(fast_tanh(e2.w + kp3), v4.w, acc2);
            acc3 = fmaf(fast_tanh(e3.w + kp3), v4.w, acc3);
        }
        sSc[(th * 4 + 0) * KK + k] = acc0;
        sSc[(th * 4 + 1) * KK + k] = acc1;
        sSc[(th * 4 + 2) * KK + k] = acc2;
        sSc[(th * 4 + 3) * KK + k] = acc3;
    }
    __syncthreads();

    // ---- phase 2: softmax over K, warp w handles row t = w (in place) ----
    {
        float* __restrict__ row = sSc + w * KK;
        float s0 = row[lane], s1 = row[lane + 32];
        float s2 = row[lane + 64], s3 = row[lane + 96];
        float m = fmaxf(fmaxf(s0, s1), fmaxf(s2, s3));
        #pragma unroll
        for (int off = 16; off; off >>= 1)
            m = fmaxf(m, __shfl_xor_sync(0xffffffffu, m, off));
        const float p0 = __expf(s0 - m), p1 = __expf(s1 - m);
        const float p2 = __expf(s2 - m), p3 = __expf(s3 - m);
        float sum = (p0 + p1) + (p2 + p3);
        #pragma unroll
        for (int off = 16; off; off >>= 1)
            sum += __shfl_xor_sync(0xffffffffu, sum, off);
        const float inv = 1.0f / sum;
        row[lane]      = p0 * inv;
        row[lane + 32] = p1 * inv;
        row[lane + 64] = p2 * inv;
        row[lane + 96] = p3 * inv;
    }
    __syncthreads();

    // ---- phase 3: context, thread = d, 8 accumulators over the t-tile ----
    {
        const float* __restrict__ knB = kn + b * KK * DK + tid;
        float cacc[TILE_T];
        #pragma unroll
        for (int i = 0; i < TILE_T; i++) cacc[i] = 0.f;

        #pragma unroll 4
        for (int k = 0; k < KK; k++) {
            const float kv = __ldg(knB + k * DK);        // coalesced, L2-hot
            #pragma unroll
            for (int i = 0; i < TILE_T; i++)
                cacc[i] = fmaf(sSc[i * KK + k], kv, cacc[i]);
        }
        float* __restrict__ oB = out + (b * TT + t0) * DK + tid;
        #pragma unroll
        for (int i = 0; i < TILE_T; i++)
            oB[i * DK] = cacc[i];
    }
}

extern "C" void kernel_launch(void* const* d_in, const int* in_sizes, int n_in,
                              void* d_out, int out_size)
{
    // metadata order: knowledge_onehot, encoder_outputs, W1, b1, W2, b2, V, bV
    const float* kn  = (const float*)d_in[0];
    const float* enc = (const float*)d_in[1];
    const float* W1  = (const float*)d_in[2];
    const float* b1  = (const float*)d_in[3];
    const float* W2  = (const float*)d_in[4];
    const float* b2  = (const float*)d_in[5];
    const float* V   = (const float*)d_in[6];
    float* out = (float*)d_out;

    const int smem = (UU * KK + TILE_T * UU + TILE_T * KK + UU) * sizeof(float);
    static bool attr_set = false;   // idempotent attribute, not a work guard
    if (!attr_set) {
        cudaFuncSetAttribute(attn_kernel, cudaFuncAttributeMaxDynamicSharedMemorySize, smem);
        attr_set = true;
    }

    prep_kernel<<<768, 128>>>(enc, kn, W1, b1, W2, b2);
    attn_kernel<<<BB * (TT / TILE_T), 256, smem>>>(kn, V, out);
}

// round 7
// speedup vs baseline: 2.2786x; 1.0846x over previous
#include <cuda_runtime.h>
#include <cuda_bf16.h>

// Problem dims (fixed by reference)
#define BB   16
#define TT   256
#define KK   128
#define DE   256
#define DK   256
#define UU   128

#define TILE_T 7
#define TPB    37                 // tiles per batch: 36*7 + 4 = 256
#define GRID_ATTN (BB * TPB)      // 592 = 4 * 148  -> one perfectly balanced wave

// Scratch (allocation-free rule -> __device__ globals; zero-initialized)
__device__ float g_E  [BB * TT * UU + 8 * UU]; // [B*T, U] enc@W1+b1, padded for ragged tail
__device__ float g_KpT[BB * UU * KK];          // [B, U, K] (kn@W2+b2)^T per batch

typedef unsigned long long u64;

__device__ __forceinline__ float fast_tanh(float x) {
    float y; asm("tanh.approx.f32 %0, %1;" : "=f"(y) : "f"(x)); return y;
}
__device__ __forceinline__ u64 pack2(float lo, float hi) {
    u64 r; asm("mov.b64 %0, {%1, %2};" : "=l"(r) : "f"(lo), "f"(hi)); return r;
}
__device__ __forceinline__ void unpack2(u64 v, float& lo, float& hi) {
    asm("mov.b64 {%0, %1}, %2;" : "=f"(lo), "=f"(hi) : "l"(v));
}
__device__ __forceinline__ u64 fma2(u64 a, u64 b, u64 c) {   // a*b + c, packed f32x2
    u64 d; asm("fma.rn.f32x2 %0, %1, %2, %3;" : "=l"(d) : "l"(a), "l"(b), "l"(c)); return d;
}

// ---------------------------------------------------------------------------
// Prologue: 8 rows per CTA, 128 threads (thread = output u). f32x2 packed.
// Blocks [0,512)  -> E rows  (4096 rows of enc[4096,256] @ W1[256,128])
// Blocks [512,768)-> Kp rows (2048 rows of kn[2048,256] @ W2[256,128]),
//                    written TRANSPOSED per batch: g_KpT[b][u][k]
// ---------------------------------------------------------------------------
__global__ void __launch_bounds__(128) prep_kernel(
    const float* __restrict__ enc, const float* __restrict__ kn,
    const float* __restrict__ W1,  const float* __restrict__ b1,
    const float* __restrict__ W2,  const float* __restrict__ b2)
{
    const bool isE   = (blockIdx.x < 512);
    const int  rbase = (isE ? blockIdx.x : (blockIdx.x - 512)) * 8;
    const float* __restrict__ X    = isE ? enc : kn;
    const float* __restrict__ W    = isE ? W1  : W2;
    const float* __restrict__ bias = isE ? b1  : b2;

    // sX[d][r], r = 0..7, padded to 10 floats/row (40B: b64-aligned, 2-way STS)
    __shared__ float sX[DE][10];
    const int tid = threadIdx.x;                 // also the output u index
    #pragma unroll
    for (int r = 0; r < 8; r++) {
        sX[tid      ][r] = X[(rbase + r) * DE + tid];
        sX[tid + 128][r] = X[(rbase + r) * DE + tid + 128];
    }
    __syncthreads();

    u64 a01 = 0, a23 = 0, a45 = 0, a67 = 0;      // bit-zero == (0.0f, 0.0f)
    #pragma unroll 4
    for (int d = 0; d < DE; d++) {
        const float w  = W[d * UU + tid];        // coalesced; L1-hot
        const u64   wd = pack2(w, w);
        const u64* __restrict__ xr = (const u64*)&sX[d][0];   // broadcast LDS.64 x4
        a01 = fma2(xr[0], wd, a01);
        a23 = fma2(xr[1], wd, a23);
        a45 = fma2(xr[2], wd, a45);
        a67 = fma2(xr[3], wd, a67);
    }
    float a[8];
    unpack2(a01, a[0], a[1]); unpack2(a23, a[2], a[3]);
    unpack2(a45, a[4], a[5]); unpack2(a67, a[6], a[7]);
    const float bb = bias[tid];

    if (isE) {
        #pragma unroll
        for (int r = 0; r < 8; r++)
            g_E[(rbase + r) * UU + tid] = a[r] + bb;
    } else {
        #pragma unroll
        for (int r = 0; r < 8; r++) {
            const int row = rbase + r;           // global knowledge row = b*K + k
            const int b = row >> 7;
            const int k = row & (KK - 1);
            g_KpT[(b * UU + tid) * KK + k] = a[r] + bb;
        }
    }
}

// ---------------------------------------------------------------------------
// Main kernel: one CTA per (b, 7-row t-tile). 256 threads, 4 CTAs/SM, 1 wave.
// smem: sE[u][8] 4KB | sA/sB[k][8] 8KB (split-u partial scores) | sV 0.5KB
//  phase 1: thread (k = tid&127, uh = tid>>7): partial score over its u-half,
//           Kp read via coalesced LDG (L2-resident), E via broadcast LDS.128.
//  phase 2: warp w (<7): softmax row t=w, summing the two u-half partials.
//  phase 3: thread = d: context via packed f32x2 FMA over t-pairs.
// ---------------------------------------------------------------------------
__global__ void __launch_bounds__(256, 4) attn_kernel(
    const float* __restrict__ kn, const float* __restrict__ V,
    float* __restrict__ out)
{
    __shared__ float sE[UU][8];     // [u][t], col 7 = pad
    __shared__ float sA[KK][8];     // u-half 0 partial scores -> attn
    __shared__ float sB[KK][8];     // u-half 1 partial scores
    __shared__ float sV[UU];

    const int tile = blockIdx.x;
    const int b    = tile / TPB;
    const int t0   = (tile - b * TPB) * TILE_T;
    const int nt   = min(TILE_T, TT - t0);       // 7, or 4 on the tail tile
    const int tid  = threadIdx.x;

    // ---- stage E tile (padded g_E makes OOB-t reads safe) + V ----
    if (tid < UU) {
        float ev[8];
        #pragma unroll
        for (int i = 0; i < 7; i++)
            ev[i] = g_E[(b * TT + t0 + i) * UU + tid];
        ev[7] = 0.f;
        float4* dst = (float4*)&sE[tid][0];
        dst[0] = make_float4(ev[0], ev[1], ev[2], ev[3]);
        dst[1] = make_float4(ev[4], ev[5], ev[6], ev[7]);
    } else {
        sV[tid - 128] = V[tid - 128];
    }
    __syncthreads();

    // ---- phase 1: partial scores over this thread's u-half ----
    {
        const int k  = tid & (KK - 1);
        const int uh = tid >> 7;                 // 0 or 1
        const float* __restrict__ kp = g_KpT + (b * UU + uh * 64) * KK + k;

        float acc[7];
        #pragma unroll
        for (int i = 0; i < 7; i++) acc[i] = 0.f;

        #pragma unroll 4
        for (int u = 0; u < 64; u++) {
            const float kpv = __ldg(kp + u * KK);         // coalesced, L2-hot
            const float vv  = sV[uh * 64 + u];            // broadcast
            const float4 e03 = *(const float4*)&sE[uh * 64 + u][0];  // broadcast
            const float4 e47 = *(const float4*)&sE[uh * 64 + u][4];
            acc[0] = fmaf(fast_tanh(e03.x + kpv), vv, acc[0]);
            acc[1] = fmaf(fast_tanh(e03.y + kpv), vv, acc[1]);
            acc[2] = fmaf(fast_tanh(e03.z + kpv), vv, acc[2]);
            acc[3] = fmaf(fast_tanh(e03.w + kpv), vv, acc[3]);
            acc[4] = fmaf(fast_tanh(e47.x + kpv), vv, acc[4]);
            acc[5] = fmaf(fast_tanh(e47.y + kpv), vv, acc[5]);
            acc[6] = fmaf(fast_tanh(e47.z + kpv), vv, acc[6]);
        }
        float4* dst = (float4*)((uh ? &sB[k][0] : &sA[k][0]));
        dst[0] = make_float4(acc[0], acc[1], acc[2], acc[3]);
        dst[1] = make_float4(acc[4], acc[5], acc[6], 0.f);   // col 7 pad = 0
    }
    __syncthreads();

    // ---- phase 2: softmax over K (warp w handles row t = w) ----
    {
        const int w = tid >> 5, lane = tid & 31;
        if (w < 7) {
            float s0 = sA[lane      ][w] + sB[lane      ][w];
            float s1 = sA[lane + 32 ][w] + sB[lane + 32 ][w];
            float s2 = sA[lane + 64 ][w] + sB[lane + 64 ][w];
            float s3 = sA[lane + 96 ][w] + sB[lane + 96 ][w];
            float m = fmaxf(fmaxf(s0, s1), fmaxf(s2, s3));
            #pragma unroll
            for (int off = 16; off; off >>= 1)
                m = fmaxf(m, __shfl_xor_sync(0xffffffffu, m, off));
            const float p0 = __expf(s0 - m), p1 = __expf(s1 - m);
            const float p2 = __expf(s2 - m), p3 = __expf(s3 - m);
            float sum = (p0 + p1) + (p2 + p3);
            #pragma unroll
            for (int off = 16; off; off >>= 1)
                sum += __shfl_xor_sync(0xffffffffu, sum, off);
            const float inv = 1.0f / sum;
            sA[lane      ][w] = p0 * inv;       // attn overwrites sA; col 7 stays 0
            sA[lane + 32 ][w] = p1 * inv;
            sA[lane + 64 ][w] = p2 * inv;
            sA[lane + 96 ][w] = p3 * inv;
        }
    }
    __syncthreads();

    // ---- phase 3: context, thread = d, packed f32x2 over t-pairs ----
    {
        const float* __restrict__ knP = kn + b * KK * DK + tid;
        u64 a01 = 0, a23 = 0, a45 = 0, a6x = 0;
        #pragma unroll 4
        for (int kk = 0; kk < KK; kk++) {
            const float kv = __ldg(knP + kk * DK);        // coalesced, L2-hot
            const u64   kd = pack2(kv, kv);
            const u64* __restrict__ at = (const u64*)&sA[kk][0];  // broadcast LDS.64 x4
            a01 = fma2(at[0], kd, a01);
            a23 = fma2(at[1], kd, a23);
            a45 = fma2(at[2], kd, a45);
            a6x = fma2(at[3], kd, a6x);                    // hi lane = pad (0)
        }
        float c[8];
        unpack2(a01, c[0], c[1]); unpack2(a23, c[2], c[3]);
        unpack2(a45, c[4], c[5]); unpack2(a6x, c[6], c[7]);

        float* __restrict__ oB = out + (b * TT + t0) * DK + tid;
        #pragma unroll
        for (int i = 0; i < 7; i++)
            if (i < nt) oB[i * DK] = c[i];
    }
}

extern "C" void kernel_launch(void* const* d_in, const int* in_sizes, int n_in,
                              void* d_out, int out_size)
{
    // metadata order: knowledge_onehot, encoder_outputs, W1, b1, W2, b2, V, bV
    const float* kn  = (const float*)d_in[0];
    const float* enc = (const float*)d_in[1];
    const float* W1  = (const float*)d_in[2];
    const float* b1  = (const float*)d_in[3];
    const float* W2  = (const float*)d_in[4];
    const float* b2  = (const float*)d_in[5];
    const float* V   = (const float*)d_in[6];
    float* out = (float*)d_out;

    prep_kernel<<<768, 128>>>(enc, kn, W1, b1, W2, b2);
    attn_kernel<<<GRID_ATTN, 256>>>(kn, V, out);
}